// round 1
// baseline (speedup 1.0000x reference)
#include <cuda_runtime.h>
#include <cuda_bf16.h>
#include <math.h>

#define NN 100000
#define EE 1600000
#define HID 128
#define NG 64
#define NC 10

// ---- scratch (no allocs allowed) ----
__device__ float g_bufA[(size_t)NN * HID];
__device__ float g_bufB[(size_t)NN * HID];
__device__ float g_agg [(size_t)NN * HID];
__device__ float g_cnt [NN];
__device__ float g_s1  [NN];
__device__ float g_invc[NN];
__device__ float g_pooled[NG * HID];
__device__ float g_gcnt[NG];

// ---------------- layer 1: scalar edge scatter (counts + sum of x[src]) ----------------
__global__ void edge_l1(const int* __restrict__ src, const int* __restrict__ dst,
                        const float* __restrict__ x, float* s1, float* cnt, int E) {
    int e = blockIdx.x * blockDim.x + threadIdx.x;
    if (e >= E) return;
    int s = src[e], d = dst[e];
    atomicAdd(&cnt[d], 1.0f);
    atomicAdd(&s1[d], x[s]);
}

// ---------------- layer 1 node kernel: h1 = relu(mean*W1l + x*W1r + b1) ----------------
__global__ void l1_node(const float* __restrict__ x, const float* __restrict__ s1,
                        const float* __restrict__ cnt, float* invc,
                        const float* __restrict__ W1l, const float* __restrict__ W1r,
                        const float* __restrict__ b1, float* __restrict__ h1, int N) {
    int idx = blockIdx.x * blockDim.x + threadIdx.x;
    if (idx >= N * HID) return;
    int n = idx >> 7, f = idx & 127;
    float ic = 1.0f / fmaxf(cnt[n], 1.0f);
    if (f == 0) invc[n] = ic;
    float v = s1[n] * ic * W1l[f] + x[n] * W1r[f] + b1[f];
    h1[idx] = fmaxf(v, 0.0f);
}

// ---------------- 128-wide edge scatter: agg[dst] += h[src] (float4 vector RED) ----------------
__global__ void scatter128(const int* __restrict__ src, const int* __restrict__ dst,
                           const float* __restrict__ h, float* __restrict__ agg, int E) {
    int gtid = blockIdx.x * blockDim.x + threadIdx.x;
    int warp = gtid >> 5;
    int lane = threadIdx.x & 31;
    int nwarps = (gridDim.x * blockDim.x) >> 5;
    for (int e = warp; e < E; e += nwarps) {
        int s = src[e], d = dst[e];
        float4 v = *reinterpret_cast<const float4*>(h + (size_t)s * HID + lane * 4);
        float* p = agg + (size_t)d * HID + lane * 4;
        asm volatile("red.global.add.v4.f32 [%0], {%1,%2,%3,%4};"
                     :: "l"(p), "f"(v.x), "f"(v.y), "f"(v.z), "f"(v.w) : "memory");
    }
}

// ---------------- fused node GEMM: out = relu([agg*invc | h] @ [Wl;Wr] + b) ----------------
// K = 256 (both weight matrices resident in smem). 64-node tile, 256 threads,
// thread tile = 8 rows x 4 cols. Conflict-free LDS.128 everywhere.
#define GEMM_SMEM (256*128*4 + 64*260*4)   // Ws[256][128] + As[64][260] = 197632 B

__global__ __launch_bounds__(256, 1)
void gemm_node(const float* __restrict__ hin, const float* __restrict__ agg,
               const float* __restrict__ invc,
               const float* __restrict__ Wl, const float* __restrict__ Wr,
               const float* __restrict__ b, float* __restrict__ hout, int N) {
    extern __shared__ float sm[];
    float* Ws = sm;                 // [k][j], pitch 128 (bank = 4*cx, conflict-free)
    float* As = sm + 256 * 128;     // [r][k], pitch 260 (warp-uniform broadcast reads)

    const int tid = threadIdx.x;
    // stage weights: k<128 -> Wl, else Wr
    for (int idx = tid; idx < 256 * 128; idx += 256) {
        int k = idx >> 7, j = idx & 127;
        Ws[idx] = (k < 128) ? Wl[k * 128 + j] : Wr[(k - 128) * 128 + j];
    }
    // stage A tile: 64 rows x 256 (agg pre-scaled by invcnt; h raw)
    const int n0 = blockIdx.x * 64;
    for (int idx = tid; idx < 64 * 256; idx += 256) {
        int r = idx >> 8, k = idx & 255;
        int n = n0 + r;
        float v = 0.0f;
        if (n < N)
            v = (k < 128) ? agg[(size_t)n * HID + k] * invc[n]
                          : hin[(size_t)n * HID + (k - 128)];
        As[r * 260 + k] = v;
    }
    __syncthreads();

    const int cx = tid & 31;      // column group: cols 4*cx .. 4*cx+3
    const int ry = tid >> 5;      // row group:    rows 8*ry .. 8*ry+7
    float acc[8][4];
#pragma unroll
    for (int i = 0; i < 8; i++)
#pragma unroll
        for (int j = 0; j < 4; j++) acc[i][j] = 0.0f;

#pragma unroll 4
    for (int k0 = 0; k0 < 256; k0 += 4) {
        float4 w0 = *reinterpret_cast<const float4*>(&Ws[(k0 + 0) * 128 + cx * 4]);
        float4 w1 = *reinterpret_cast<const float4*>(&Ws[(k0 + 1) * 128 + cx * 4]);
        float4 w2 = *reinterpret_cast<const float4*>(&Ws[(k0 + 2) * 128 + cx * 4]);
        float4 w3 = *reinterpret_cast<const float4*>(&Ws[(k0 + 3) * 128 + cx * 4]);
#pragma unroll
        for (int rr = 0; rr < 8; rr++) {
            float4 a = *reinterpret_cast<const float4*>(&As[(ry * 8 + rr) * 260 + k0]);
            acc[rr][0] += a.x * w0.x + a.y * w1.x + a.z * w2.x + a.w * w3.x;
            acc[rr][1] += a.x * w0.y + a.y * w1.y + a.z * w2.y + a.w * w3.y;
            acc[rr][2] += a.x * w0.z + a.y * w1.z + a.z * w2.z + a.w * w3.z;
            acc[rr][3] += a.x * w0.w + a.y * w1.w + a.z * w2.w + a.w * w3.w;
        }
    }

    float4 bias = *reinterpret_cast<const float4*>(&b[cx * 4]);
#pragma unroll
    for (int rr = 0; rr < 8; rr++) {
        int n = n0 + ry * 8 + rr;
        if (n < N) {
            float4 o;
            o.x = fmaxf(acc[rr][0] + bias.x, 0.0f);
            o.y = fmaxf(acc[rr][1] + bias.y, 0.0f);
            o.z = fmaxf(acc[rr][2] + bias.z, 0.0f);
            o.w = fmaxf(acc[rr][3] + bias.w, 0.0f);
            *reinterpret_cast<float4*>(&hout[(size_t)n * HID + cx * 4]) = o;
        }
    }
}

// ---------------- global mean pool (batch is sorted -> run-length, few atomics) ----------------
__global__ void pool_kernel(const float* __restrict__ h, const int* __restrict__ batch,
                            float* pooled, float* gcnt, int N) {
    const int f = threadIdx.x;           // 128 threads, one feature each
    int start = blockIdx.x * 512;
    if (start >= N) return;
    int end = min(start + 512, N);
    float acc = 0.0f, run = 0.0f;
    int gprev = batch[start];
    for (int n = start; n < end; n++) {
        int g = batch[n];
        if (g != gprev) {
            atomicAdd(&pooled[gprev * HID + f], acc);
            if (f == 0) atomicAdd(&gcnt[gprev], run);
            acc = 0.0f; run = 0.0f; gprev = g;
        }
        acc += h[(size_t)n * HID + f];
        run += 1.0f;
    }
    atomicAdd(&pooled[gprev * HID + f], acc);
    if (f == 0) atomicAdd(&gcnt[gprev], run);
}

// ---------------- final FC + log_softmax ----------------
__global__ void final_kernel(const float* __restrict__ pooled, const float* __restrict__ gcnt,
                             const float* __restrict__ Wfc, const float* __restrict__ bfc,
                             float* __restrict__ out) {
    __shared__ float sl[NG * NC];
    int t = threadIdx.x;
    if (t < NG * NC) {
        int g = t / NC, c = t % NC;
        float inv = 1.0f / fmaxf(gcnt[g], 1.0f);
        float s = bfc[c];
#pragma unroll 8
        for (int k = 0; k < HID; k++)
            s += pooled[g * HID + k] * inv * Wfc[k * NC + c];
        sl[t] = s;
    }
    __syncthreads();
    if (t < NG * NC) {
        int g = t / NC;
        float m = -1e30f;
        for (int c2 = 0; c2 < NC; c2++) m = fmaxf(m, sl[g * NC + c2]);
        float sum = 0.0f;
        for (int c2 = 0; c2 < NC; c2++) sum += __expf(sl[g * NC + c2] - m);
        out[t] = sl[t] - m - logf(sum);
    }
}

extern "C" void kernel_launch(void* const* d_in, const int* in_sizes, int n_in,
                              void* d_out, int out_size) {
    const float* x    = (const float*)d_in[0];
    const int*   ei   = (const int*)  d_in[1];
    const int*   batch= (const int*)  d_in[2];
    const float* W1l  = (const float*)d_in[3];
    const float* W1r  = (const float*)d_in[4];
    const float* b1   = (const float*)d_in[5];
    const float* W2l  = (const float*)d_in[6];
    const float* W2r  = (const float*)d_in[7];
    const float* b2   = (const float*)d_in[8];
    const float* W3l  = (const float*)d_in[9];
    const float* W3r  = (const float*)d_in[10];
    const float* b3   = (const float*)d_in[11];
    const float* Wfc  = (const float*)d_in[12];
    const float* bfc  = (const float*)d_in[13];
    float* out = (float*)d_out;

    const int N = in_sizes[0];        // 100000
    const int E = in_sizes[1] / 2;    // 1600000
    const int* src = ei;
    const int* dst = ei + E;

    float *bufA, *bufB, *agg, *cnt, *s1, *invc, *pooled, *gcnt;
    cudaGetSymbolAddress((void**)&bufA,   g_bufA);
    cudaGetSymbolAddress((void**)&bufB,   g_bufB);
    cudaGetSymbolAddress((void**)&agg,    g_agg);
    cudaGetSymbolAddress((void**)&cnt,    g_cnt);
    cudaGetSymbolAddress((void**)&s1,     g_s1);
    cudaGetSymbolAddress((void**)&invc,   g_invc);
    cudaGetSymbolAddress((void**)&pooled, g_pooled);
    cudaGetSymbolAddress((void**)&gcnt,   g_gcnt);

    cudaFuncSetAttribute(gemm_node, cudaFuncAttributeMaxDynamicSharedMemorySize, GEMM_SMEM);

    cudaMemsetAsync(cnt,    0, (size_t)N * sizeof(float));
    cudaMemsetAsync(s1,     0, (size_t)N * sizeof(float));
    cudaMemsetAsync(pooled, 0, NG * HID * sizeof(float));
    cudaMemsetAsync(gcnt,   0, NG * sizeof(float));

    // layer 1
    edge_l1<<<(E + 255) / 256, 256>>>(src, dst, x, s1, cnt, E);
    l1_node<<<((size_t)N * HID + 255) / 256, 256>>>(x, s1, cnt, invc, W1l, W1r, b1, bufA, N);

    // layer 2
    cudaMemsetAsync(agg, 0, (size_t)N * HID * sizeof(float));
    scatter128<<<16384, 256>>>(src, dst, bufA, agg, E);
    gemm_node<<<(N + 63) / 64, 256, GEMM_SMEM>>>(bufA, agg, invc, W2l, W2r, b2, bufB, N);

    // layer 3
    cudaMemsetAsync(agg, 0, (size_t)N * HID * sizeof(float));
    scatter128<<<16384, 256>>>(src, dst, bufB, agg, E);
    gemm_node<<<(N + 63) / 64, 256, GEMM_SMEM>>>(bufB, agg, invc, W3l, W3r, b3, bufA, N);

    // pool + classifier
    pool_kernel<<<(N + 511) / 512, 128>>>(bufA, batch, pooled, gcnt, N);
    final_kernel<<<1, NG * NC>>>(pooled, gcnt, Wfc, bfc, out);
}

// round 3
// speedup vs baseline: 1.8817x; 1.8817x over previous
#include <cuda_runtime.h>
#include <cuda_bf16.h>
#include <mma.h>
#include <math.h>
#include <cstdint>

using namespace nvcuda;

#define NN 100000
#define EE 1600000
#define HID 128
#define NG 64
#define NC 10

// ---- scratch (no allocs allowed) ----
__device__ float g_bufA[(size_t)NN * HID];
__device__ float g_bufB[(size_t)NN * HID];
__device__ float g_agg [(size_t)NN * HID];
__device__ float g_cnt [NN];
__device__ float g_s1  [NN];
__device__ float g_invc[NN];
__device__ float g_pooled[NG * HID];
__device__ float g_gcnt[NG];

// halfword0 = bf16(a), halfword1 = bf16(b)
__device__ __forceinline__ uint32_t pack_bf16x2(float a, float b) {
    uint32_t r;
    asm("cvt.rn.bf16x2.f32 %0, %1, %2;" : "=r"(r) : "f"(b), "f"(a));
    return r;
}

// =================== layer 1 (rank-1) ===================
__global__ void edge_l1(const int* __restrict__ src, const int* __restrict__ dst,
                        const float* __restrict__ x, float* s1, float* cnt, int E) {
    int e = blockIdx.x * blockDim.x + threadIdx.x;
    if (e >= E) return;
    int s = src[e], d = dst[e];
    atomicAdd(&cnt[d], 1.0f);
    atomicAdd(&s1[d], x[s]);
}

__global__ void l1_node(const float* __restrict__ x, const float* __restrict__ s1,
                        const float* __restrict__ cnt, float* invc,
                        const float* __restrict__ W1l, const float* __restrict__ W1r,
                        const float* __restrict__ b1, float* __restrict__ h1, int N) {
    int idx = blockIdx.x * blockDim.x + threadIdx.x;
    if (idx >= N * HID) return;
    int n = idx >> 7, f = idx & 127;
    float ic = 1.0f / fmaxf(cnt[n], 1.0f);
    if (f == 0) invc[n] = ic;
    float v = s1[n] * ic * W1l[f] + x[n] * W1r[f] + b1[f];
    h1[idx] = fmaxf(v, 0.0f);
}

// =================== 128-wide edge scatter (float4 vector RED) ===================
__global__ void scatter128(const int* __restrict__ src, const int* __restrict__ dst,
                           const float* __restrict__ h, float* __restrict__ agg, int E) {
    int gtid = blockIdx.x * blockDim.x + threadIdx.x;
    int warp = gtid >> 5;
    int lane = threadIdx.x & 31;
    int nwarps = (gridDim.x * blockDim.x) >> 5;
    for (int e = warp; e < E; e += nwarps) {
        int s = src[e], d = dst[e];
        float4 v = *reinterpret_cast<const float4*>(h + (size_t)s * HID + lane * 4);
        float* p = agg + (size_t)d * HID + lane * 4;
        asm volatile("red.global.add.v4.f32 [%0], {%1,%2,%3,%4};"
                     :: "l"(p), "f"(v.x), "f"(v.y), "f"(v.z), "f"(v.w) : "memory");
    }
}

// =================== wmma node GEMM ===================
// D[128 nodes x 64 feats] = [mean | h] (K=256) @ W[:, j0:j0+64], fp32 via 3 bf16
// passes (Ahi*Whi + Ahi*Wlo + Alo*Whi). K processed in 2 chunks of 128
// (chunk 0 = mean/Wl, chunk 1 = h/Wr) so smem stays at ~104 KB -> 2 CTAs/SM.
//
// smem layout (bytes):
//   AH [128][136] bf16 @ 0        (34816)
//   AL [128][136] bf16 @ 34816    (34816)
//   WH [128][72]  bf16 @ 69632    (18432)
//   WL [128][72]  bf16 @ 88064    (18432)   total 106496
//   D  [128][72]  f32  @ 0 (overlay, epilogue only)
#define A_STRIDE 136
#define W_STRIDE 72
#define AH_OFF 0
#define AL_OFF 34816
#define WH_OFF 69632
#define WL_OFF 88064
#define GEMM_SMEM 106496

__global__ __launch_bounds__(256)
void gemm_wmma(const float* __restrict__ hin, const float* __restrict__ agg,
               const float* __restrict__ invc,
               const float* __restrict__ Wl, const float* __restrict__ Wr,
               const float* __restrict__ bias, float* __restrict__ hout, int N) {
    extern __shared__ char smem[];
    __nv_bfloat16* AH = reinterpret_cast<__nv_bfloat16*>(smem + AH_OFF);
    __nv_bfloat16* AL = reinterpret_cast<__nv_bfloat16*>(smem + AL_OFF);
    __nv_bfloat16* WH = reinterpret_cast<__nv_bfloat16*>(smem + WH_OFF);
    __nv_bfloat16* WL = reinterpret_cast<__nv_bfloat16*>(smem + WL_OFF);

    const int tid = threadIdx.x;
    const int wid = tid >> 5;
    const int wm  = wid >> 1;      // 0..3: rows wm*32..+31
    const int wn  = wid & 1;       // 0..1: cols wn*32..+31
    const int n0 = blockIdx.x * 128;
    const int j0 = blockIdx.y * 64;

    wmma::fragment<wmma::accumulator, 16, 16, 16, float> acc[2][2];
#pragma unroll
    for (int i = 0; i < 2; i++)
#pragma unroll
        for (int j = 0; j < 2; j++) wmma::fill_fragment(acc[i][j], 0.0f);

#pragma unroll
    for (int chunk = 0; chunk < 2; chunk++) {
        __syncthreads();   // protect smem from previous chunk's in-flight reads

        // ---- stage A half: 128 rows x 128 K (fp32 -> hi/lo bf16) ----
        for (int idx = tid; idx < 128 * 32; idx += 256) {
            int r  = idx >> 5;
            int kq = (idx & 31) * 4;
            int n  = n0 + r;
            float4 v = make_float4(0.f, 0.f, 0.f, 0.f);
            if (n < N) {
                if (chunk == 0) {
                    float ic = invc[n];
                    float4 t = *reinterpret_cast<const float4*>(agg + (size_t)n * HID + kq);
                    v = make_float4(t.x * ic, t.y * ic, t.z * ic, t.w * ic);
                } else {
                    v = *reinterpret_cast<const float4*>(hin + (size_t)n * HID + kq);
                }
            }
            uint32_t h01 = pack_bf16x2(v.x, v.y);
            uint32_t h23 = pack_bf16x2(v.z, v.w);
            float f0 = __uint_as_float(h01 << 16);
            float f1 = __uint_as_float(h01 & 0xFFFF0000u);
            float f2 = __uint_as_float(h23 << 16);
            float f3 = __uint_as_float(h23 & 0xFFFF0000u);
            uint32_t l01 = pack_bf16x2(v.x - f0, v.y - f1);
            uint32_t l23 = pack_bf16x2(v.z - f2, v.w - f3);
            *reinterpret_cast<uint2*>(AH + r * A_STRIDE + kq) = make_uint2(h01, h23);
            *reinterpret_cast<uint2*>(AL + r * A_STRIDE + kq) = make_uint2(l01, l23);
        }

        // ---- stage W half: 128 k-rows x 64 features ----
        const float* Wsrc = (chunk == 0) ? Wl : Wr;
        for (int idx = tid; idx < 128 * 16; idx += 256) {
            int k  = idx >> 4;
            int jq = (idx & 15) * 4;
            float4 v = *reinterpret_cast<const float4*>(Wsrc + (size_t)k * HID + j0 + jq);
            uint32_t h01 = pack_bf16x2(v.x, v.y);
            uint32_t h23 = pack_bf16x2(v.z, v.w);
            float f0 = __uint_as_float(h01 << 16);
            float f1 = __uint_as_float(h01 & 0xFFFF0000u);
            float f2 = __uint_as_float(h23 << 16);
            float f3 = __uint_as_float(h23 & 0xFFFF0000u);
            uint32_t l01 = pack_bf16x2(v.x - f0, v.y - f1);
            uint32_t l23 = pack_bf16x2(v.z - f2, v.w - f3);
            *reinterpret_cast<uint2*>(WH + k * W_STRIDE + jq) = make_uint2(h01, h23);
            *reinterpret_cast<uint2*>(WL + k * W_STRIDE + jq) = make_uint2(l01, l23);
        }
        __syncthreads();

        // ---- 3 passes x 8 K-steps of wmma ----
#pragma unroll
        for (int pass = 0; pass < 3; pass++) {
            const __nv_bfloat16* pA = (pass == 2) ? AL : AH;
            const __nv_bfloat16* pB = (pass == 1) ? WL : WH;
#pragma unroll
            for (int k0 = 0; k0 < 128; k0 += 16) {
                wmma::fragment<wmma::matrix_a, 16, 16, 16, __nv_bfloat16, wmma::row_major> a0, a1;
                wmma::fragment<wmma::matrix_b, 16, 16, 16, __nv_bfloat16, wmma::row_major> b0, b1;
                wmma::load_matrix_sync(a0, pA + (wm * 32 +  0) * A_STRIDE + k0, A_STRIDE);
                wmma::load_matrix_sync(a1, pA + (wm * 32 + 16) * A_STRIDE + k0, A_STRIDE);
                wmma::load_matrix_sync(b0, pB + k0 * W_STRIDE + wn * 32 +  0, W_STRIDE);
                wmma::load_matrix_sync(b1, pB + k0 * W_STRIDE + wn * 32 + 16, W_STRIDE);
                wmma::mma_sync(acc[0][0], a0, b0, acc[0][0]);
                wmma::mma_sync(acc[0][1], a0, b1, acc[0][1]);
                wmma::mma_sync(acc[1][0], a1, b0, acc[1][0]);
                wmma::mma_sync(acc[1][1], a1, b1, acc[1][1]);
            }
        }
    }

    // ---- epilogue: stage D to smem (overlay), then bias+relu+store ----
    __syncthreads();
    float* Ds = reinterpret_cast<float*>(smem);   // [128][72]
#pragma unroll
    for (int i = 0; i < 2; i++)
#pragma unroll
        for (int j = 0; j < 2; j++)
            wmma::store_matrix_sync(Ds + (wm * 32 + i * 16) * 72 + wn * 32 + j * 16,
                                    acc[i][j], 72, wmma::mem_row_major);
    __syncthreads();

    for (int idx = tid; idx < 128 * 16; idx += 256) {
        int r  = idx >> 4;
        int jq = (idx & 15) * 4;
        int n  = n0 + r;
        if (n < N) {
            float4 d = *reinterpret_cast<const float4*>(Ds + r * 72 + jq);
            float4 bb = *reinterpret_cast<const float4*>(bias + j0 + jq);
            float4 o;
            o.x = fmaxf(d.x + bb.x, 0.0f);
            o.y = fmaxf(d.y + bb.y, 0.0f);
            o.z = fmaxf(d.z + bb.z, 0.0f);
            o.w = fmaxf(d.w + bb.w, 0.0f);
            *reinterpret_cast<float4*>(hout + (size_t)n * HID + j0 + jq) = o;
        }
    }
}

// =================== pool + classifier ===================
__global__ void pool_kernel(const float* __restrict__ h, const int* __restrict__ batch,
                            float* pooled, float* gcnt, int N) {
    const int f = threadIdx.x;
    int start = blockIdx.x * 512;
    if (start >= N) return;
    int end = min(start + 512, N);
    float acc = 0.0f, run = 0.0f;
    int gprev = batch[start];
    for (int n = start; n < end; n++) {
        int g = batch[n];
        if (g != gprev) {
            atomicAdd(&pooled[gprev * HID + f], acc);
            if (f == 0) atomicAdd(&gcnt[gprev], run);
            acc = 0.0f; run = 0.0f; gprev = g;
        }
        acc += h[(size_t)n * HID + f];
        run += 1.0f;
    }
    atomicAdd(&pooled[gprev * HID + f], acc);
    if (f == 0) atomicAdd(&gcnt[gprev], run);
}

__global__ void final_kernel(const float* __restrict__ pooled, const float* __restrict__ gcnt,
                             const float* __restrict__ Wfc, const float* __restrict__ bfc,
                             float* __restrict__ out) {
    __shared__ float sl[NG * NC];
    int t = threadIdx.x;
    if (t < NG * NC) {
        int g = t / NC, c = t % NC;
        float inv = 1.0f / fmaxf(gcnt[g], 1.0f);
        float s = bfc[c];
#pragma unroll 8
        for (int k = 0; k < HID; k++)
            s += pooled[g * HID + k] * inv * Wfc[k * NC + c];
        sl[t] = s;
    }
    __syncthreads();
    if (t < NG * NC) {
        int g = t / NC;
        float m = -1e30f;
        for (int c2 = 0; c2 < NC; c2++) m = fmaxf(m, sl[g * NC + c2]);
        float sum = 0.0f;
        for (int c2 = 0; c2 < NC; c2++) sum += __expf(sl[g * NC + c2] - m);
        out[t] = sl[t] - m - logf(sum);
    }
}

extern "C" void kernel_launch(void* const* d_in, const int* in_sizes, int n_in,
                              void* d_out, int out_size) {
    const float* x    = (const float*)d_in[0];
    const int*   ei   = (const int*)  d_in[1];
    const int*   batch= (const int*)  d_in[2];
    const float* W1l  = (const float*)d_in[3];
    const float* W1r  = (const float*)d_in[4];
    const float* b1   = (const float*)d_in[5];
    const float* W2l  = (const float*)d_in[6];
    const float* W2r  = (const float*)d_in[7];
    const float* b2   = (const float*)d_in[8];
    const float* W3l  = (const float*)d_in[9];
    const float* W3r  = (const float*)d_in[10];
    const float* b3   = (const float*)d_in[11];
    const float* Wfc  = (const float*)d_in[12];
    const float* bfc  = (const float*)d_in[13];
    float* out = (float*)d_out;

    const int N = in_sizes[0];
    const int E = in_sizes[1] / 2;
    const int* src = ei;
    const int* dst = ei + E;

    float *bufA, *bufB, *agg, *cnt, *s1, *invc, *pooled, *gcnt;
    cudaGetSymbolAddress((void**)&bufA,   g_bufA);
    cudaGetSymbolAddress((void**)&bufB,   g_bufB);
    cudaGetSymbolAddress((void**)&agg,    g_agg);
    cudaGetSymbolAddress((void**)&cnt,    g_cnt);
    cudaGetSymbolAddress((void**)&s1,     g_s1);
    cudaGetSymbolAddress((void**)&invc,   g_invc);
    cudaGetSymbolAddress((void**)&pooled, g_pooled);
    cudaGetSymbolAddress((void**)&gcnt,   g_gcnt);

    cudaFuncSetAttribute(gemm_wmma, cudaFuncAttributeMaxDynamicSharedMemorySize, GEMM_SMEM);

    cudaMemsetAsync(cnt,    0, (size_t)N * sizeof(float));
    cudaMemsetAsync(s1,     0, (size_t)N * sizeof(float));
    cudaMemsetAsync(pooled, 0, NG * HID * sizeof(float));
    cudaMemsetAsync(gcnt,   0, NG * sizeof(float));

    // layer 1 (rank-1)
    edge_l1<<<(E + 255) / 256, 256>>>(src, dst, x, s1, cnt, E);
    l1_node<<<((size_t)N * HID + 255) / 256, 256>>>(x, s1, cnt, invc, W1l, W1r, b1, bufA, N);

    dim3 ggrid((N + 127) / 128, 2);

    // layer 2
    cudaMemsetAsync(agg, 0, (size_t)N * HID * sizeof(float));
    scatter128<<<16384, 256>>>(src, dst, bufA, agg, E);
    gemm_wmma<<<ggrid, 256, GEMM_SMEM>>>(bufA, agg, invc, W2l, W2r, b2, bufB, N);

    // layer 3
    cudaMemsetAsync(agg, 0, (size_t)N * HID * sizeof(float));
    scatter128<<<16384, 256>>>(src, dst, bufB, agg, E);
    gemm_wmma<<<ggrid, 256, GEMM_SMEM>>>(bufB, agg, invc, W3l, W3r, b3, bufA, N);

    // pool + classifier
    pool_kernel<<<(N + 511) / 512, 128>>>(bufA, batch, pooled, gcnt, N);
    final_kernel<<<1, NG * NC>>>(pooled, gcnt, Wfc, bfc, out);
}